// round 12
// baseline (speedup 1.0000x reference)
#include <cuda_runtime.h>
#include <cuda_fp16.h>
#include <math.h>
#include <stdint.h>

#define NTOK  16384
#define NHEAD 16
#define DHEAD 128
#define HID   512
#define DTOT  2048

typedef __half fh;

// ---------------- scratch (device globals; no allocs allowed) ----------------
static __device__ fh g_xh[(size_t)NTOK * DTOT];
static __device__ fh g_ah[(size_t)NHEAD * NTOK * HID];
static __device__ fh g_bh[(size_t)NHEAD * NTOK * HID];
static __device__ fh g_w0[(size_t)NHEAD * HID * DHEAD];
static __device__ fh g_w1[(size_t)NHEAD * HID * HID];
static __device__ fh g_w2[(size_t)NHEAD * HID * HID];
static __device__ fh g_w3[(size_t)NHEAD * DHEAD * HID];

// ---------------- helpers ----------------
__device__ __forceinline__ uint32_t smem_u32(const void* p) {
    uint32_t a;
    asm("{ .reg .u64 t; cvta.to.shared.u64 t, %1; cvt.u32.u64 %0, t; }"
        : "=r"(a) : "l"(p));
    return a;
}
__device__ __forceinline__ float gelu_f(float x) {
    return 0.5f * x * (1.0f + erff(x * 0.70710678118654752f));
}
__device__ __forceinline__ uint32_t packh(fh a, fh b) {
    return (uint32_t)__half_as_ushort(a) | ((uint32_t)__half_as_ushort(b) << 16);
}

__device__ __forceinline__ void ldsm4(uint32_t (&r)[4], uint32_t addr) {
    asm volatile("ldmatrix.sync.aligned.m8n8.x4.shared.b16 {%0,%1,%2,%3}, [%4];"
                 : "=r"(r[0]), "=r"(r[1]), "=r"(r[2]), "=r"(r[3]) : "r"(addr));
}
__device__ __forceinline__ void mma16816(float (&d)[4], const uint32_t (&a)[4],
                                         uint32_t b0, uint32_t b1) {
    asm volatile(
        "mma.sync.aligned.m16n8k16.row.col.f32.f16.f16.f32 "
        "{%0,%1,%2,%3}, {%4,%5,%6,%7}, {%8,%9}, {%0,%1,%2,%3};"
        : "+f"(d[0]), "+f"(d[1]), "+f"(d[2]), "+f"(d[3])
        : "r"(a[0]), "r"(a[1]), "r"(a[2]), "r"(a[3]), "r"(b0), "r"(b1));
}

// cp.async 16B tile loader: ROWS x 64 fp16 (128B rows), XOR-8 chunk swizzle
template <int ROWS>
__device__ __forceinline__ void ldt(uint32_t sbase, const fh* g, int ldg_, int tid) {
#pragma unroll
    for (int q = tid; q < ROWS * 8; q += 256) {
        int r = q >> 3, c8 = q & 7;
        uint32_t dst = sbase + r * 128 + ((c8 ^ (r & 7)) << 4);
        const char* src = (const char*)(g + (size_t)r * ldg_) + c8 * 16;
        asm volatile("cp.async.cg.shared.global [%0], [%1], 16;"
                     :: "r"(dst), "l"(src) : "memory");
    }
}

// =======================================================================
// HMMA fp16 GEMM, BK=64, NS=3, register-double-buffered fragments.
// Hazard design (one barrier per chunk, at iteration bottom):
//   bottom barrier of iter c  = wait_group(0) + __syncthreads()
//     RAW: publishes stages c+1 (read at iter c+1 s<3 and its s==3 pre-read
//          at iter c) ... stage c+1 was published by iter c-1's barrier;
//          stage c+2 published here for iter c+1's s==3 prefetch.
//     WAR: fences all reads of stage c before iter c+3 overwrites it; the
//          ldt for chunk c+2 is issued at iter c s==0, AFTER iter c-1's
//          bottom barrier fenced the last reads of stage (c-1)%3.
//   s==3 prefetch of (chunk c+1, s=0) overlaps the s==3 MMAs — R8's
//   schedule, now race-free.
// D[BM x BN] = Ah[BM x K] @ Bh[BN x K]^T.
//   BM=128, BN=256: warp grid 2(M) x 4(N), warp tile 64x64  (L0..L2)
//   BM=256, BN=128: warp grid 4(M) x 2(N), warp tile 64x64  (L3)
// OMODE: 1 = raw fp32 -> Cf, 2 = gelu -> fp16 -> Ch
// 256 threads, 1 CTA/SM, 144KB dynamic smem.
// =======================================================================
template <int BM, int BN, int OMODE>
__global__ __launch_bounds__(256, 1)
void hgemm_kernel(const fh* __restrict__ Ah, size_t aHead, int lda,
                  const fh* __restrict__ Bh, size_t bHead, int K,
                  fh* __restrict__ Ch, float* __restrict__ Cf,
                  size_t cHead, int ldc) {
    extern __shared__ char smem[];
    const uint32_t sb = smem_u32(smem);
    const int tid = threadIdx.x, wid = tid >> 5, lane = tid & 31;
    const int h = blockIdx.z;
    const int m0 = blockIdx.x * BM;
    const int n0 = blockIdx.y * BN;

    constexpr int NS = 3;
    constexpr uint32_t TILE_A = (uint32_t)BM * 128;
    constexpr uint32_t TILE_B = (uint32_t)BN * 128;
    constexpr uint32_t STAGE = TILE_A + TILE_B;    // 48KB both shapes

    const fh* gAh = Ah + h * aHead + (size_t)m0 * lda;
    const fh* gBh = Bh + h * bHead + (size_t)n0 * K;

    // warp tile 64x64
    const int wm = (BM == 128) ? (wid & 1) * 64 : (wid & 3) * 64;
    const int wn = (BM == 128) ? (wid >> 1) * 64 : (wid >> 2) * 64;

    int arow[4], brow[4];
#pragma unroll
    for (int mi = 0; mi < 4; mi++) arow[mi] = wm + mi * 16 + (lane & 15);
#pragma unroll
    for (int bj = 0; bj < 4; bj++)
        brow[bj] = wn + bj * 16 + ((lane >> 3) & 1) * 8 + (lane & 7);
    const int hi16 = lane >> 4;

    float acc[4][8][4];
#pragma unroll
    for (int i = 0; i < 4; i++)
#pragma unroll
        for (int j = 0; j < 8; j++)
#pragma unroll
            for (int e = 0; e < 4; e++) acc[i][j][e] = 0.f;

    const int KT = K >> 6;

    // preload chunks 0 and 1 (stages 0, 1)
#pragma unroll
    for (int p = 0; p < NS - 1; p++) {
        if (p < KT) {
            const uint32_t st = sb + (uint32_t)p * STAGE;
            const int k0 = p * 64;
            ldt<BM>(st, gAh + k0, lda, tid);
            ldt<BN>(st + TILE_A, gBh + k0, K, tid);
        }
        asm volatile("cp.async.commit_group;" ::: "memory");
    }

    uint32_t ahf[2][4][4], bhf[2][4][4];

#define LOADFRAGS(buf, stbase, sstep)                                           \
    do {                                                                        \
        const int c2_ = (sstep) * 2 + hi16;                                     \
        _Pragma("unroll")                                                       \
        for (int mi_ = 0; mi_ < 4; mi_++)                                       \
            ldsm4(ahf[buf][mi_],                                                \
                  (stbase) + arow[mi_] * 128 + ((c2_ ^ (arow[mi_] & 7)) << 4)); \
        _Pragma("unroll")                                                       \
        for (int bj_ = 0; bj_ < 4; bj_++)                                       \
            ldsm4(bhf[buf][bj_],                                                \
                  (stbase) + TILE_A + brow[bj_] * 128 +                         \
                  ((c2_ ^ (brow[bj_] & 7)) << 4));                              \
    } while (0)

    // prime: chunks 0 and 1 complete AND published, then (chunk 0, s=0) frags
    asm volatile("cp.async.wait_group 0;" ::: "memory");
    __syncthreads();
    LOADFRAGS(0, sb, 0);

    for (int c = 0; c < KT; c++) {
        const uint32_t st = sb + (uint32_t)(c % NS) * STAGE;
#pragma unroll
        for (int s = 0; s < 4; s++) {
            const int cur = s & 1, nxt = cur ^ 1;
            if (s == 0) {
                // issue loads for chunk c+2 (WAR-safe: prior bottom barrier)
                const int cn = c + 2;
                if (cn < KT) {
                    const uint32_t sn = sb + (uint32_t)(cn % NS) * STAGE;
                    const int k0 = cn * 64;
                    ldt<BM>(sn, gAh + k0, lda, tid);
                    ldt<BN>(sn + TILE_A, gBh + k0, K, tid);
                }
                asm volatile("cp.async.commit_group;" ::: "memory");
            }
            if (s < 3) {
                LOADFRAGS(nxt, st, s + 1);
            } else if (c + 1 < KT) {
                // overlapped cross-chunk prefetch; stage c+1 was published by
                // the PREVIOUS bottom barrier (or the prime) -> race-free
                LOADFRAGS(nxt, sb + (uint32_t)((c + 1) % NS) * STAGE, 0);
            }
#pragma unroll
            for (int mi = 0; mi < 4; mi++)
#pragma unroll
                for (int bj = 0; bj < 4; bj++) {
                    mma16816(acc[mi][2 * bj],     ahf[cur][mi],
                             bhf[cur][bj][0], bhf[cur][bj][2]);
                    mma16816(acc[mi][2 * bj + 1], ahf[cur][mi],
                             bhf[cur][bj][1], bhf[cur][bj][3]);
                }
        }
        // bottom barrier: publish stage c+2, fence reads of stage c (WAR)
        if (c + 1 < KT) {
            asm volatile("cp.async.wait_group 0;" ::: "memory");
            __syncthreads();
        }
    }
#undef LOADFRAGS

    // ---------------- epilogue ----------------
    const int rbase = (lane >> 2);
    const int cbase = (lane & 3) * 2;

#pragma unroll
    for (int mi = 0; mi < 4; mi++) {
#pragma unroll
        for (int nj = 0; nj < 8; nj++) {
#pragma unroll
            for (int half = 0; half < 2; half++) {
                const size_t m = (size_t)m0 + wm + mi * 16 + rbase + half * 8;
                const int col = n0 + wn + nj * 8 + cbase;
                float v0 = acc[mi][nj][2 * half];
                float v1 = acc[mi][nj][2 * half + 1];
                if (OMODE == 2) {
                    v0 = gelu_f(v0);
                    v1 = gelu_f(v1);
                    *reinterpret_cast<uint32_t*>(Ch + h * cHead + m * ldc + col) =
                        packh(__float2half_rn(v0), __float2half_rn(v1));
                } else {
                    *reinterpret_cast<float2*>(Cf + h * cHead + m * ldc + col) =
                        make_float2(v0, v1);
                }
            }
        }
    }
}

// ---------------- RMSNorm -> fp16 (hi only) ----------------
__global__ void rms_kernel(const float* __restrict__ x, const float* __restrict__ g,
                           fh* __restrict__ xh) {
    const int row = blockIdx.x, tid = threadIdx.x;
    const float4* xr = reinterpret_cast<const float4*>(x + (size_t)row * DTOT);
    float4 a = xr[tid], b = xr[tid + 256];
    float s = a.x * a.x + a.y * a.y + a.z * a.z + a.w * a.w +
              b.x * b.x + b.y * b.y + b.z * b.z + b.w * b.w;
#pragma unroll
    for (int o = 16; o; o >>= 1) s += __shfl_xor_sync(0xffffffffu, s, o);
    __shared__ float ws[8];
    __shared__ float srs;
    if ((tid & 31) == 0) ws[tid >> 5] = s;
    __syncthreads();
    if (tid == 0) {
        float t = 0.f;
#pragma unroll
        for (int i = 0; i < 8; i++) t += ws[i];
        srs = rsqrtf(t * (1.0f / DTOT) + 1.1920929e-7f);
    }
    __syncthreads();
    const float rs = srs;
    const float4* gr = reinterpret_cast<const float4*>(g);
    float4 ga = gr[tid], gb = gr[tid + 256];

    float va[8] = {a.x * rs * ga.x, a.y * rs * ga.y, a.z * rs * ga.z, a.w * rs * ga.w,
                   b.x * rs * gb.x, b.y * rs * gb.y, b.z * rs * gb.z, b.w * rs * gb.w};
    size_t base = (size_t)row * DTOT;
#pragma unroll
    for (int half = 0; half < 2; half++) {
        size_t o = base + (size_t)(tid + half * 256) * 4;
        uint32_t hp[2];
#pragma unroll
        for (int j = 0; j < 2; j++)
            hp[j] = packh(__float2half_rn(va[half * 4 + 2 * j]),
                          __float2half_rn(va[half * 4 + 2 * j + 1]));
        *reinterpret_cast<uint2*>(xh + o) = make_uint2(hp[0], hp[1]);
    }
}

// ---------------- weight transpose to fp16: W[z][K][N] -> O[z][N][K] ----------------
__global__ void wsplit_kernel(const float* __restrict__ W, int K, int N,
                              fh* __restrict__ Oh) {
    __shared__ float t[32][33];
    const int z = blockIdx.z;
    const int k0 = blockIdx.x * 32, n0 = blockIdx.y * 32;
    const int tx = threadIdx.x & 31, ty = threadIdx.x >> 5;
    const float* Wb = W + (size_t)z * K * N;
#pragma unroll
    for (int i = 0; i < 4; i++)
        t[ty + i * 8][tx] = Wb[(size_t)(k0 + ty + i * 8) * N + n0 + tx];
    __syncthreads();
#pragma unroll
    for (int i = 0; i < 4; i++) {
        int n = n0 + ty + i * 8, k = k0 + tx;
        size_t o = ((size_t)z * N + n) * K + k;
        Oh[o] = __float2half_rn(t[tx][ty + i * 8]);
    }
}

// batched variant for w1 + w2 (same shape)
__global__ void wsplit2_kernel(const float* __restrict__ W1, const float* __restrict__ W2,
                               fh* __restrict__ O1, fh* __restrict__ O2) {
    __shared__ float t[32][33];
    const int z = blockIdx.z;                 // 0..31: low 16 = w1 heads, high = w2
    const float* W = (z < NHEAD) ? W1 : W2;
    fh* O = (z < NHEAD) ? O1 : O2;
    const int h = (z < NHEAD) ? z : z - NHEAD;
    const int k0 = blockIdx.x * 32, n0 = blockIdx.y * 32;
    const int tx = threadIdx.x & 31, ty = threadIdx.x >> 5;
    const float* Wb = W + (size_t)h * HID * HID;
#pragma unroll
    for (int i = 0; i < 4; i++)
        t[ty + i * 8][tx] = Wb[(size_t)(k0 + ty + i * 8) * HID + n0 + tx];
    __syncthreads();
#pragma unroll
    for (int i = 0; i < 4; i++) {
        int n = n0 + ty + i * 8, k = k0 + tx;
        size_t o = ((size_t)h * HID + n) * HID + k;
        O[o] = __float2half_rn(t[tx][ty + i * 8]);
    }
}

// ---------------- launch ----------------
extern "C" void kernel_launch(void* const* d_in, const int* in_sizes, int n_in,
                              void* d_out, int out_size) {
    const float* x  = (const float*)d_in[0];
    const float* g  = (const float*)d_in[1];
    const float* w0 = (const float*)d_in[2];
    const float* w1 = (const float*)d_in[3];
    const float* w2 = (const float*)d_in[4];
    const float* w3 = (const float*)d_in[5];
    float* out = (float*)d_out;

    fh *xh, *ah, *bh, *pw0, *pw1, *pw2, *pw3;
    cudaGetSymbolAddress((void**)&xh, g_xh);
    cudaGetSymbolAddress((void**)&ah, g_ah);
    cudaGetSymbolAddress((void**)&bh, g_bh);
    cudaGetSymbolAddress((void**)&pw0, g_w0);
    cudaGetSymbolAddress((void**)&pw1, g_w1);
    cudaGetSymbolAddress((void**)&pw2, g_w2);
    cudaGetSymbolAddress((void**)&pw3, g_w3);

    constexpr int SMEM = 3 * (128 * 128 + 256 * 128);  // 147456 (both shapes)
    cudaFuncSetAttribute(hgemm_kernel<128, 256, 2>,
                         cudaFuncAttributeMaxDynamicSharedMemorySize, SMEM);
    cudaFuncSetAttribute(hgemm_kernel<256, 128, 1>,
                         cudaFuncAttributeMaxDynamicSharedMemorySize, SMEM);

    // prep
    rms_kernel<<<NTOK, 256>>>(x, g, xh);
    wsplit_kernel<<<dim3(DHEAD / 32, HID / 32, NHEAD), 256>>>(w0, DHEAD, HID, pw0);
    wsplit2_kernel<<<dim3(HID / 32, HID / 32, 2 * NHEAD), 256>>>(w1, w2, pw1, pw2);
    wsplit_kernel<<<dim3(HID / 32, DHEAD / 32, NHEAD), 256>>>(w3, HID, DHEAD, pw3);

    const size_t actHead = (size_t)NTOK * HID;

    // L0: a = gelu( xn[:,h] @ w0[h] )
    hgemm_kernel<128, 256, 2><<<dim3(NTOK / 128, HID / 256, NHEAD), 256, SMEM>>>(
        xh, (size_t)DHEAD, DTOT, pw0, (size_t)HID * DHEAD, DHEAD,
        ah, nullptr, actHead, HID);
    // L1: b = gelu( a @ w1[h] )
    hgemm_kernel<128, 256, 2><<<dim3(NTOK / 128, HID / 256, NHEAD), 256, SMEM>>>(
        ah, actHead, HID, pw1, (size_t)HID * HID, HID,
        bh, nullptr, actHead, HID);
    // L2: a = gelu( b @ w2[h] )
    hgemm_kernel<128, 256, 2><<<dim3(NTOK / 128, HID / 256, NHEAD), 256, SMEM>>>(
        bh, actHead, HID, pw2, (size_t)HID * HID, HID,
        ah, nullptr, actHead, HID);
    // L3: out[:,h] = a @ w3[h]   BM=256 fast path, fp32 out
    hgemm_kernel<256, 128, 1><<<dim3(NTOK / 256, DHEAD / 128, NHEAD), 256, SMEM>>>(
        ah, actHead, HID, pw3, (size_t)DHEAD * HID, HID,
        nullptr, out, (size_t)DHEAD, DTOT);
}

// round 13
// speedup vs baseline: 1.0508x; 1.0508x over previous
#include <cuda_runtime.h>
#include <cuda_fp16.h>
#include <math.h>
#include <stdint.h>

#define NTOK  16384
#define NHEAD 16
#define DHEAD 128
#define HID   512
#define DTOT  2048

typedef __half fh;

// ---------------- scratch (device globals; no allocs allowed) ----------------
static __device__ fh g_xh[(size_t)NTOK * DTOT];
static __device__ fh g_ah[(size_t)NHEAD * NTOK * HID];
static __device__ fh g_bh[(size_t)NHEAD * NTOK * HID];
static __device__ fh g_w0[(size_t)NHEAD * HID * DHEAD];
static __device__ fh g_w1[(size_t)NHEAD * HID * HID];
static __device__ fh g_w2[(size_t)NHEAD * HID * HID];
static __device__ fh g_w3[(size_t)NHEAD * DHEAD * HID];

// ---------------- helpers ----------------
__device__ __forceinline__ uint32_t smem_u32(const void* p) {
    uint32_t a;
    asm("{ .reg .u64 t; cvta.to.shared.u64 t, %1; cvt.u32.u64 %0, t; }"
        : "=r"(a) : "l"(p));
    return a;
}
__device__ __forceinline__ float gelu_f(float x) {
    return 0.5f * x * (1.0f + erff(x * 0.70710678118654752f));
}
__device__ __forceinline__ uint32_t packh(fh a, fh b) {
    return (uint32_t)__half_as_ushort(a) | ((uint32_t)__half_as_ushort(b) << 16);
}

__device__ __forceinline__ void ldsm4(uint32_t (&r)[4], uint32_t addr) {
    asm volatile("ldmatrix.sync.aligned.m8n8.x4.shared.b16 {%0,%1,%2,%3}, [%4];"
                 : "=r"(r[0]), "=r"(r[1]), "=r"(r[2]), "=r"(r[3]) : "r"(addr));
}
__device__ __forceinline__ void mma16816(float (&d)[4], const uint32_t (&a)[4],
                                         uint32_t b0, uint32_t b1) {
    asm volatile(
        "mma.sync.aligned.m16n8k16.row.col.f32.f16.f16.f32 "
        "{%0,%1,%2,%3}, {%4,%5,%6,%7}, {%8,%9}, {%0,%1,%2,%3};"
        : "+f"(d[0]), "+f"(d[1]), "+f"(d[2]), "+f"(d[3])
        : "r"(a[0]), "r"(a[1]), "r"(a[2]), "r"(a[3]), "r"(b0), "r"(b1));
}

// cp.async 16B tile loader: ROWS x 64 fp16 (128B rows), XOR-8 chunk swizzle
template <int ROWS>
__device__ __forceinline__ void ldt(uint32_t sbase, const fh* g, int ldg_, int tid) {
#pragma unroll
    for (int q = tid; q < ROWS * 8; q += 256) {
        int r = q >> 3, c8 = q & 7;
        uint32_t dst = sbase + r * 128 + ((c8 ^ (r & 7)) << 4);
        const char* src = (const char*)(g + (size_t)r * ldg_) + c8 * 16;
        asm volatile("cp.async.cg.shared.global [%0], [%1], 16;"
                     :: "r"(dst), "l"(src) : "memory");
    }
}

// =======================================================================
// HMMA fp16 GEMM, BK=64, NS=3, register-double-buffered fragments.
// Sync design: ONE barrier per chunk at the TOP of s==3:
//   wait_group(1): outstanding = {chunk c+1 (issued iter c-1), chunk c+2
//   (issued iter c s==0)}; waits only for c+1, which has had >= 1 full
//   chunk of compute to land -> ~zero stall. __syncthreads publishes it
//   (RAW) and fences this chunk's stage reads before the NEXT iteration's
//   s==0 cp.async overwrite (WAR). The s==3 cross-chunk prefetch then
//   overlaps the s==3 MMAs (registers already loaded at s==2).
// D[BM x BN] = Ah[BM x K] @ Bh[BN x K]^T.
//   BM=128, BN=256: warp grid 2(M) x 4(N), warp tile 64x64  (L0..L2)
//   BM=256, BN=128: warp grid 4(M) x 2(N), warp tile 64x64  (L3)
// OMODE: 1 = raw fp32 -> Cf, 2 = gelu -> fp16 -> Ch
// 256 threads, 1 CTA/SM, 144KB dynamic smem.
// =======================================================================
template <int BM, int BN, int OMODE>
__global__ __launch_bounds__(256, 1)
void hgemm_kernel(const fh* __restrict__ Ah, size_t aHead, int lda,
                  const fh* __restrict__ Bh, size_t bHead, int K,
                  fh* __restrict__ Ch, float* __restrict__ Cf,
                  size_t cHead, int ldc) {
    extern __shared__ char smem[];
    const uint32_t sb = smem_u32(smem);
    const int tid = threadIdx.x, wid = tid >> 5, lane = tid & 31;
    const int h = blockIdx.z;
    const int m0 = blockIdx.x * BM;
    const int n0 = blockIdx.y * BN;

    constexpr int NS = 3;
    constexpr uint32_t TILE_A = (uint32_t)BM * 128;
    constexpr uint32_t TILE_B = (uint32_t)BN * 128;
    constexpr uint32_t STAGE = TILE_A + TILE_B;    // 48KB both shapes

    const fh* gAh = Ah + h * aHead + (size_t)m0 * lda;
    const fh* gBh = Bh + h * bHead + (size_t)n0 * K;

    // warp tile 64x64
    const int wm = (BM == 128) ? (wid & 1) * 64 : (wid & 3) * 64;
    const int wn = (BM == 128) ? (wid >> 1) * 64 : (wid >> 2) * 64;

    int arow[4], brow[4];
#pragma unroll
    for (int mi = 0; mi < 4; mi++) arow[mi] = wm + mi * 16 + (lane & 15);
#pragma unroll
    for (int bj = 0; bj < 4; bj++)
        brow[bj] = wn + bj * 16 + ((lane >> 3) & 1) * 8 + (lane & 7);
    const int hi16 = lane >> 4;

    float acc[4][8][4];
#pragma unroll
    for (int i = 0; i < 4; i++)
#pragma unroll
        for (int j = 0; j < 8; j++)
#pragma unroll
            for (int e = 0; e < 4; e++) acc[i][j][e] = 0.f;

    const int KT = K >> 6;

    // preload chunks 0 and 1 (stages 0, 1), one commit group each
#pragma unroll
    for (int p = 0; p < NS - 1; p++) {
        if (p < KT) {
            const uint32_t st = sb + (uint32_t)p * STAGE;
            const int k0 = p * 64;
            ldt<BM>(st, gAh + k0, lda, tid);
            ldt<BN>(st + TILE_A, gBh + k0, K, tid);
        }
        asm volatile("cp.async.commit_group;" ::: "memory");
    }

    uint32_t ahf[2][4][4], bhf[2][4][4];

#define LOADFRAGS(buf, stbase, sstep)                                           \
    do {                                                                        \
        const int c2_ = (sstep) * 2 + hi16;                                     \
        _Pragma("unroll")                                                       \
        for (int mi_ = 0; mi_ < 4; mi_++)                                       \
            ldsm4(ahf[buf][mi_],                                                \
                  (stbase) + arow[mi_] * 128 + ((c2_ ^ (arow[mi_] & 7)) << 4)); \
        _Pragma("unroll")                                                       \
        for (int bj_ = 0; bj_ < 4; bj_++)                                       \
            ldsm4(bhf[buf][bj_],                                                \
                  (stbase) + TILE_A + brow[bj_] * 128 +                         \
                  ((c2_ ^ (brow[bj_] & 7)) << 4));                              \
    } while (0)

    // prime: chunk 0 complete AND published (chunk 1 handled at iter 0 s==3)
    asm volatile("cp.async.wait_group 1;" ::: "memory");
    __syncthreads();
    LOADFRAGS(0, sb, 0);

    for (int c = 0; c < KT; c++) {
        const uint32_t st = sb + (uint32_t)(c % NS) * STAGE;
#pragma unroll
        for (int s = 0; s < 4; s++) {
            const int cur = s & 1, nxt = cur ^ 1;
            if (s == 0) {
                // issue loads for chunk c+2 (WAR-safe: prior iter's s==3
                // barrier fenced the last reads of this stage)
                const int cn = c + 2;
                if (cn < KT) {
                    const uint32_t sn = sb + (uint32_t)(cn % NS) * STAGE;
                    const int k0 = cn * 64;
                    ldt<BM>(sn, gAh + k0, lda, tid);
                    ldt<BN>(sn + TILE_A, gBh + k0, K, tid);
                }
                asm volatile("cp.async.commit_group;" ::: "memory");
            }
            if (s < 3) {
                LOADFRAGS(nxt, st, s + 1);
            } else if (c + 1 < KT) {
                // barrier: wait chunk c+1 (>=1 chunk of slack), publish it,
                // and fence this chunk's smem reads (WAR for next s==0 ldt)
                asm volatile("cp.async.wait_group 1;" ::: "memory");
                __syncthreads();
                // overlapped cross-chunk prefetch of (chunk c+1, s=0)
                LOADFRAGS(nxt, sb + (uint32_t)((c + 1) % NS) * STAGE, 0);
            }
#pragma unroll
            for (int mi = 0; mi < 4; mi++)
#pragma unroll
                for (int bj = 0; bj < 4; bj++) {
                    mma16816(acc[mi][2 * bj],     ahf[cur][mi],
                             bhf[cur][bj][0], bhf[cur][bj][2]);
                    mma16816(acc[mi][2 * bj + 1], ahf[cur][mi],
                             bhf[cur][bj][1], bhf[cur][bj][3]);
                }
        }
    }
#undef LOADFRAGS

    // ---------------- epilogue ----------------
    const int rbase = (lane >> 2);
    const int cbase = (lane & 3) * 2;

#pragma unroll
    for (int mi = 0; mi < 4; mi++) {
#pragma unroll
        for (int nj = 0; nj < 8; nj++) {
#pragma unroll
            for (int half = 0; half < 2; half++) {
                const size_t m = (size_t)m0 + wm + mi * 16 + rbase + half * 8;
                const int col = n0 + wn + nj * 8 + cbase;
                float v0 = acc[mi][nj][2 * half];
                float v1 = acc[mi][nj][2 * half + 1];
                if (OMODE == 2) {
                    v0 = gelu_f(v0);
                    v1 = gelu_f(v1);
                    *reinterpret_cast<uint32_t*>(Ch + h * cHead + m * ldc + col) =
                        packh(__float2half_rn(v0), __float2half_rn(v1));
                } else {
                    *reinterpret_cast<float2*>(Cf + h * cHead + m * ldc + col) =
                        make_float2(v0, v1);
                }
            }
        }
    }
}

// ---------------- RMSNorm -> fp16 (hi only) ----------------
__global__ void rms_kernel(const float* __restrict__ x, const float* __restrict__ g,
                           fh* __restrict__ xh) {
    const int row = blockIdx.x, tid = threadIdx.x;
    const float4* xr = reinterpret_cast<const float4*>(x + (size_t)row * DTOT);
    float4 a = xr[tid], b = xr[tid + 256];
    float s = a.x * a.x + a.y * a.y + a.z * a.z + a.w * a.w +
              b.x * b.x + b.y * b.y + b.z * b.z + b.w * b.w;
#pragma unroll
    for (int o = 16; o; o >>= 1) s += __shfl_xor_sync(0xffffffffu, s, o);
    __shared__ float ws[8];
    __shared__ float srs;
    if ((tid & 31) == 0) ws[tid >> 5] = s;
    __syncthreads();
    if (tid == 0) {
        float t = 0.f;
#pragma unroll
        for (int i = 0; i < 8; i++) t += ws[i];
        srs = rsqrtf(t * (1.0f / DTOT) + 1.1920929e-7f);
    }
    __syncthreads();
    const float rs = srs;
    const float4* gr = reinterpret_cast<const float4*>(g);
    float4 ga = gr[tid], gb = gr[tid + 256];

    float va[8] = {a.x * rs * ga.x, a.y * rs * ga.y, a.z * rs * ga.z, a.w * rs * ga.w,
                   b.x * rs * gb.x, b.y * rs * gb.y, b.z * rs * gb.z, b.w * rs * gb.w};
    size_t base = (size_t)row * DTOT;
#pragma unroll
    for (int half = 0; half < 2; half++) {
        size_t o = base + (size_t)(tid + half * 256) * 4;
        uint32_t hp[2];
#pragma unroll
        for (int j = 0; j < 2; j++)
            hp[j] = packh(__float2half_rn(va[half * 4 + 2 * j]),
                          __float2half_rn(va[half * 4 + 2 * j + 1]));
        *reinterpret_cast<uint2*>(xh + o) = make_uint2(hp[0], hp[1]);
    }
}

// ---------------- weight transpose to fp16: W[z][K][N] -> O[z][N][K] ----------------
__global__ void wsplit_kernel(const float* __restrict__ W, int K, int N,
                              fh* __restrict__ Oh) {
    __shared__ float t[32][33];
    const int z = blockIdx.z;
    const int k0 = blockIdx.x * 32, n0 = blockIdx.y * 32;
    const int tx = threadIdx.x & 31, ty = threadIdx.x >> 5;
    const float* Wb = W + (size_t)z * K * N;
#pragma unroll
    for (int i = 0; i < 4; i++)
        t[ty + i * 8][tx] = Wb[(size_t)(k0 + ty + i * 8) * N + n0 + tx];
    __syncthreads();
#pragma unroll
    for (int i = 0; i < 4; i++) {
        int n = n0 + ty + i * 8, k = k0 + tx;
        size_t o = ((size_t)z * N + n) * K + k;
        Oh[o] = __float2half_rn(t[tx][ty + i * 8]);
    }
}

// batched variant for w1 + w2 (same shape)
__global__ void wsplit2_kernel(const float* __restrict__ W1, const float* __restrict__ W2,
                               fh* __restrict__ O1, fh* __restrict__ O2) {
    __shared__ float t[32][33];
    const int z = blockIdx.z;                 // 0..31: low 16 = w1 heads, high = w2
    const float* W = (z < NHEAD) ? W1 : W2;
    fh* O = (z < NHEAD) ? O1 : O2;
    const int h = (z < NHEAD) ? z : z - NHEAD;
    const int k0 = blockIdx.x * 32, n0 = blockIdx.y * 32;
    const int tx = threadIdx.x & 31, ty = threadIdx.x >> 5;
    const float* Wb = W + (size_t)h * HID * HID;
#pragma unroll
    for (int i = 0; i < 4; i++)
        t[ty + i * 8][tx] = Wb[(size_t)(k0 + ty + i * 8) * HID + n0 + tx];
    __syncthreads();
#pragma unroll
    for (int i = 0; i < 4; i++) {
        int n = n0 + ty + i * 8, k = k0 + tx;
        size_t o = ((size_t)h * HID + n) * HID + k;
        O[o] = __float2half_rn(t[tx][ty + i * 8]);
    }
}

// ---------------- launch ----------------
extern "C" void kernel_launch(void* const* d_in, const int* in_sizes, int n_in,
                              void* d_out, int out_size) {
    const float* x  = (const float*)d_in[0];
    const float* g  = (const float*)d_in[1];
    const float* w0 = (const float*)d_in[2];
    const float* w1 = (const float*)d_in[3];
    const float* w2 = (const float*)d_in[4];
    const float* w3 = (const float*)d_in[5];
    float* out = (float*)d_out;

    fh *xh, *ah, *bh, *pw0, *pw1, *pw2, *pw3;
    cudaGetSymbolAddress((void**)&xh, g_xh);
    cudaGetSymbolAddress((void**)&ah, g_ah);
    cudaGetSymbolAddress((void**)&bh, g_bh);
    cudaGetSymbolAddress((void**)&pw0, g_w0);
    cudaGetSymbolAddress((void**)&pw1, g_w1);
    cudaGetSymbolAddress((void**)&pw2, g_w2);
    cudaGetSymbolAddress((void**)&pw3, g_w3);

    constexpr int SMEM = 3 * (128 * 128 + 256 * 128);  // 147456 (both shapes)
    cudaFuncSetAttribute(hgemm_kernel<128, 256, 2>,
                         cudaFuncAttributeMaxDynamicSharedMemorySize, SMEM);
    cudaFuncSetAttribute(hgemm_kernel<256, 128, 1>,
                         cudaFuncAttributeMaxDynamicSharedMemorySize, SMEM);

    // prep
    rms_kernel<<<NTOK, 256>>>(x, g, xh);
    wsplit_kernel<<<dim3(DHEAD / 32, HID / 32, NHEAD), 256>>>(w0, DHEAD, HID, pw0);
    wsplit2_kernel<<<dim3(HID / 32, HID / 32, 2 * NHEAD), 256>>>(w1, w2, pw1, pw2);
    wsplit_kernel<<<dim3(HID / 32, DHEAD / 32, NHEAD), 256>>>(w3, HID, DHEAD, pw3);

    const size_t actHead = (size_t)NTOK * HID;

    // L0: a = gelu( xn[:,h] @ w0[h] )
    hgemm_kernel<128, 256, 2><<<dim3(NTOK / 128, HID / 256, NHEAD), 256, SMEM>>>(
        xh, (size_t)DHEAD, DTOT, pw0, (size_t)HID * DHEAD, DHEAD,
        ah, nullptr, actHead, HID);
    // L1: b = gelu( a @ w1[h] )
    hgemm_kernel<128, 256, 2><<<dim3(NTOK / 128, HID / 256, NHEAD), 256, SMEM>>>(
        ah, actHead, HID, pw1, (size_t)HID * HID, HID,
        bh, nullptr, actHead, HID);
    // L2: a = gelu( b @ w2[h] )
    hgemm_kernel<128, 256, 2><<<dim3(NTOK / 128, HID / 256, NHEAD), 256, SMEM>>>(
        bh, actHead, HID, pw2, (size_t)HID * HID, HID,
        ah, nullptr, actHead, HID);
    // L3: out[:,h] = a @ w3[h]   BM=256 fast path, fp32 out
    hgemm_kernel<256, 128, 1><<<dim3(NTOK / 256, DHEAD / 128, NHEAD), 256, SMEM>>>(
        ah, actHead, HID, pw3, (size_t)DHEAD * HID, HID,
        nullptr, out, (size_t)DHEAD, DTOT);
}

// round 14
// speedup vs baseline: 1.1642x; 1.1079x over previous
#include <cuda_runtime.h>
#include <cuda_fp16.h>
#include <math.h>
#include <stdint.h>

#define NTOK  16384
#define NHEAD 16
#define DHEAD 128
#define HID   512
#define DTOT  2048

typedef __half fh;

// ---------------- scratch (device globals; no allocs allowed) ----------------
static __device__ fh g_xh[(size_t)NTOK * DTOT];
static __device__ fh g_ah[(size_t)NHEAD * NTOK * HID];
static __device__ fh g_bh[(size_t)NHEAD * NTOK * HID];
static __device__ fh g_w0[(size_t)NHEAD * HID * DHEAD];
static __device__ fh g_w1[(size_t)NHEAD * HID * HID];
static __device__ fh g_w2[(size_t)NHEAD * HID * HID];
static __device__ fh g_w3[(size_t)NHEAD * DHEAD * HID];

// ---------------- helpers ----------------
__device__ __forceinline__ uint32_t smem_u32(const void* p) {
    uint32_t a;
    asm("{ .reg .u64 t; cvta.to.shared.u64 t, %1; cvt.u32.u64 %0, t; }"
        : "=r"(a) : "l"(p));
    return a;
}
__device__ __forceinline__ float gelu_f(float x) {
    return 0.5f * x * (1.0f + erff(x * 0.70710678118654752f));
}
__device__ __forceinline__ uint32_t packh(fh a, fh b) {
    return (uint32_t)__half_as_ushort(a) | ((uint32_t)__half_as_ushort(b) << 16);
}

__device__ __forceinline__ void ldsm4(uint32_t (&r)[4], uint32_t addr) {
    asm volatile("ldmatrix.sync.aligned.m8n8.x4.shared.b16 {%0,%1,%2,%3}, [%4];"
                 : "=r"(r[0]), "=r"(r[1]), "=r"(r[2]), "=r"(r[3]) : "r"(addr));
}
__device__ __forceinline__ void mma16816(float (&d)[4], const uint32_t (&a)[4],
                                         uint32_t b0, uint32_t b1) {
    asm volatile(
        "mma.sync.aligned.m16n8k16.row.col.f32.f16.f16.f32 "
        "{%0,%1,%2,%3}, {%4,%5,%6,%7}, {%8,%9}, {%0,%1,%2,%3};"
        : "+f"(d[0]), "+f"(d[1]), "+f"(d[2]), "+f"(d[3])
        : "r"(a[0]), "r"(a[1]), "r"(a[2]), "r"(a[3]), "r"(b0), "r"(b1));
}

// cp.async 16B tile loader: ROWS x 64 fp16 (128B rows), XOR-8 chunk swizzle
// NT = threads in block
template <int ROWS, int NT>
__device__ __forceinline__ void ldt(uint32_t sbase, const fh* g, int ldg_, int tid) {
#pragma unroll
    for (int q = tid; q < ROWS * 8; q += NT) {
        int r = q >> 3, c8 = q & 7;
        uint32_t dst = sbase + r * 128 + ((c8 ^ (r & 7)) << 4);
        const char* src = (const char*)(g + (size_t)r * ldg_) + c8 * 16;
        asm volatile("cp.async.cg.shared.global [%0], [%1], 16;"
                     :: "r"(dst), "l"(src) : "memory");
    }
}

// =======================================================================
// HMMA fp16 GEMM: D[128 x 128] = Ah[128 x K] @ Bh[128 x K]^T
// 128 threads (4 warps), warp grid 2(M) x 2(N), warp tile 64x64.
// BK=64, NS=3, fragment double-buffer, R13-legal sync schedule:
//   - chunk c+2 cp.async issued at s==0 (WAR-safe: previous s==3 barrier)
//   - s==3: wait_group(1) + __syncthreads (publishes chunk c+1, fences
//     stage-c reads), then overlapped prefetch of (c+1, s=0) fragments.
// occ=2 (96KB smem/CTA, <=256 regs/thread): the sibling CTA covers
// barrier/refill bubbles that occ=1 variants exposed.
// OMODE: 1 = raw fp32 -> Cf, 2 = gelu -> fp16 -> Ch
// =======================================================================
template <int OMODE>
__global__ __launch_bounds__(128, 2)
void hgemm_kernel(const fh* __restrict__ Ah, size_t aHead, int lda,
                  const fh* __restrict__ Bh, size_t bHead, int K,
                  fh* __restrict__ Ch, float* __restrict__ Cf,
                  size_t cHead, int ldc) {
    extern __shared__ char smem[];
    const uint32_t sb = smem_u32(smem);
    const int tid = threadIdx.x, wid = tid >> 5, lane = tid & 31;
    const int h = blockIdx.z;
    const int m0 = blockIdx.x * 128;
    const int n0 = blockIdx.y * 128;

    constexpr int NS = 3;
    constexpr uint32_t TILE_A = 128 * 128;   // 16KB
    constexpr uint32_t TILE_B = 128 * 128;   // 16KB
    constexpr uint32_t STAGE = TILE_A + TILE_B;  // 32KB

    const fh* gAh = Ah + h * aHead + (size_t)m0 * lda;
    const fh* gBh = Bh + h * bHead + (size_t)n0 * K;

    // warp tile 64x64, warp grid 2(M) x 2(N)
    const int wm = (wid & 1) * 64;
    const int wn = (wid >> 1) * 64;

    int arow[4], brow[4];
#pragma unroll
    for (int mi = 0; mi < 4; mi++) arow[mi] = wm + mi * 16 + (lane & 15);
#pragma unroll
    for (int bj = 0; bj < 4; bj++)
        brow[bj] = wn + bj * 16 + ((lane >> 3) & 1) * 8 + (lane & 7);
    const int hi16 = lane >> 4;

    float acc[4][8][4];
#pragma unroll
    for (int i = 0; i < 4; i++)
#pragma unroll
        for (int j = 0; j < 8; j++)
#pragma unroll
            for (int e = 0; e < 4; e++) acc[i][j][e] = 0.f;

    const int KT = K >> 6;

    // preload chunks 0 and 1 (stages 0, 1), one commit group each
#pragma unroll
    for (int p = 0; p < NS - 1; p++) {
        if (p < KT) {
            const uint32_t st = sb + (uint32_t)p * STAGE;
            const int k0 = p * 64;
            ldt<128, 128>(st, gAh + k0, lda, tid);
            ldt<128, 128>(st + TILE_A, gBh + k0, K, tid);
        }
        asm volatile("cp.async.commit_group;" ::: "memory");
    }

    uint32_t ahf[2][4][4], bhf[2][4][4];

#define LOADFRAGS(buf, stbase, sstep)                                           \
    do {                                                                        \
        const int c2_ = (sstep) * 2 + hi16;                                     \
        _Pragma("unroll")                                                       \
        for (int mi_ = 0; mi_ < 4; mi_++)                                       \
            ldsm4(ahf[buf][mi_],                                                \
                  (stbase) + arow[mi_] * 128 + ((c2_ ^ (arow[mi_] & 7)) << 4)); \
        _Pragma("unroll")                                                       \
        for (int bj_ = 0; bj_ < 4; bj_++)                                       \
            ldsm4(bhf[buf][bj_],                                                \
                  (stbase) + TILE_A + brow[bj_] * 128 +                         \
                  ((c2_ ^ (brow[bj_] & 7)) << 4));                              \
    } while (0)

    // prime: chunk 0 complete AND published
    asm volatile("cp.async.wait_group 1;" ::: "memory");
    __syncthreads();
    LOADFRAGS(0, sb, 0);

    for (int c = 0; c < KT; c++) {
        const uint32_t st = sb + (uint32_t)(c % NS) * STAGE;
#pragma unroll
        for (int s = 0; s < 4; s++) {
            const int cur = s & 1, nxt = cur ^ 1;
            if (s == 0) {
                // issue loads for chunk c+2 (WAR-safe: prior s==3 barrier)
                const int cn = c + 2;
                if (cn < KT) {
                    const uint32_t sn = sb + (uint32_t)(cn % NS) * STAGE;
                    const int k0 = cn * 64;
                    ldt<128, 128>(sn, gAh + k0, lda, tid);
                    ldt<128, 128>(sn + TILE_A, gBh + k0, K, tid);
                }
                asm volatile("cp.async.commit_group;" ::: "memory");
            }
            if (s < 3) {
                LOADFRAGS(nxt, st, s + 1);
            } else if (c + 1 < KT) {
                // wait chunk c+1 (>=1 chunk slack), publish + WAR fence
                asm volatile("cp.async.wait_group 1;" ::: "memory");
                __syncthreads();
                // overlapped cross-chunk prefetch of (chunk c+1, s=0)
                LOADFRAGS(nxt, sb + (uint32_t)((c + 1) % NS) * STAGE, 0);
            }
#pragma unroll
            for (int mi = 0; mi < 4; mi++)
#pragma unroll
                for (int bj = 0; bj < 4; bj++) {
                    mma16816(acc[mi][2 * bj],     ahf[cur][mi],
                             bhf[cur][bj][0], bhf[cur][bj][2]);
                    mma16816(acc[mi][2 * bj + 1], ahf[cur][mi],
                             bhf[cur][bj][1], bhf[cur][bj][3]);
                }
        }
    }
#undef LOADFRAGS

    // ---------------- epilogue ----------------
    const int rbase = (lane >> 2);
    const int cbase = (lane & 3) * 2;

#pragma unroll
    for (int mi = 0; mi < 4; mi++) {
#pragma unroll
        for (int nj = 0; nj < 8; nj++) {
#pragma unroll
            for (int half = 0; half < 2; half++) {
                const size_t m = (size_t)m0 + wm + mi * 16 + rbase + half * 8;
                const int col = n0 + wn + nj * 8 + cbase;
                float v0 = acc[mi][nj][2 * half];
                float v1 = acc[mi][nj][2 * half + 1];
                if (OMODE == 2) {
                    v0 = gelu_f(v0);
                    v1 = gelu_f(v1);
                    *reinterpret_cast<uint32_t*>(Ch + h * cHead + m * ldc + col) =
                        packh(__float2half_rn(v0), __float2half_rn(v1));
                } else {
                    *reinterpret_cast<float2*>(Cf + h * cHead + m * ldc + col) =
                        make_float2(v0, v1);
                }
            }
        }
    }
}

// ---------------- RMSNorm -> fp16 (hi only) ----------------
__global__ void rms_kernel(const float* __restrict__ x, const float* __restrict__ g,
                           fh* __restrict__ xh) {
    const int row = blockIdx.x, tid = threadIdx.x;
    const float4* xr = reinterpret_cast<const float4*>(x + (size_t)row * DTOT);
    float4 a = xr[tid], b = xr[tid + 256];
    float s = a.x * a.x + a.y * a.y + a.z * a.z + a.w * a.w +
              b.x * b.x + b.y * b.y + b.z * b.z + b.w * b.w;
#pragma unroll
    for (int o = 16; o; o >>= 1) s += __shfl_xor_sync(0xffffffffu, s, o);
    __shared__ float ws[8];
    __shared__ float srs;
    if ((tid & 31) == 0) ws[tid >> 5] = s;
    __syncthreads();
    if (tid == 0) {
        float t = 0.f;
#pragma unroll
        for (int i = 0; i < 8; i++) t += ws[i];
        srs = rsqrtf(t * (1.0f / DTOT) + 1.1920929e-7f);
    }
    __syncthreads();
    const float rs = srs;
    const float4* gr = reinterpret_cast<const float4*>(g);
    float4 ga = gr[tid], gb = gr[tid + 256];

    float va[8] = {a.x * rs * ga.x, a.y * rs * ga.y, a.z * rs * ga.z, a.w * rs * ga.w,
                   b.x * rs * gb.x, b.y * rs * gb.y, b.z * rs * gb.z, b.w * rs * gb.w};
    size_t base = (size_t)row * DTOT;
#pragma unroll
    for (int half = 0; half < 2; half++) {
        size_t o = base + (size_t)(tid + half * 256) * 4;
        uint32_t hp[2];
#pragma unroll
        for (int j = 0; j < 2; j++)
            hp[j] = packh(__float2half_rn(va[half * 4 + 2 * j]),
                          __float2half_rn(va[half * 4 + 2 * j + 1]));
        *reinterpret_cast<uint2*>(xh + o) = make_uint2(hp[0], hp[1]);
    }
}

// ---------------- weight transpose to fp16: W[z][K][N] -> O[z][N][K] ----------------
__global__ void wsplit_kernel(const float* __restrict__ W, int K, int N,
                              fh* __restrict__ Oh) {
    __shared__ float t[32][33];
    const int z = blockIdx.z;
    const int k0 = blockIdx.x * 32, n0 = blockIdx.y * 32;
    const int tx = threadIdx.x & 31, ty = threadIdx.x >> 5;
    const float* Wb = W + (size_t)z * K * N;
#pragma unroll
    for (int i = 0; i < 4; i++)
        t[ty + i * 8][tx] = Wb[(size_t)(k0 + ty + i * 8) * N + n0 + tx];
    __syncthreads();
#pragma unroll
    for (int i = 0; i < 4; i++) {
        int n = n0 + ty + i * 8, k = k0 + tx;
        size_t o = ((size_t)z * N + n) * K + k;
        Oh[o] = __float2half_rn(t[tx][ty + i * 8]);
    }
}

// batched variant for w1 + w2 (same shape)
__global__ void wsplit2_kernel(const float* __restrict__ W1, const float* __restrict__ W2,
                               fh* __restrict__ O1, fh* __restrict__ O2) {
    __shared__ float t[32][33];
    const int z = blockIdx.z;                 // 0..31: low 16 = w1 heads, high = w2
    const float* W = (z < NHEAD) ? W1 : W2;
    fh* O = (z < NHEAD) ? O1 : O2;
    const int h = (z < NHEAD) ? z : z - NHEAD;
    const int k0 = blockIdx.x * 32, n0 = blockIdx.y * 32;
    const int tx = threadIdx.x & 31, ty = threadIdx.x >> 5;
    const float* Wb = W + (size_t)h * HID * HID;
#pragma unroll
    for (int i = 0; i < 4; i++)
        t[ty + i * 8][tx] = Wb[(size_t)(k0 + ty + i * 8) * HID + n0 + tx];
    __syncthreads();
#pragma unroll
    for (int i = 0; i < 4; i++) {
        int n = n0 + ty + i * 8, k = k0 + tx;
        size_t o = ((size_t)h * HID + n) * HID + k;
        O[o] = __float2half_rn(t[tx][ty + i * 8]);
    }
}

// ---------------- launch ----------------
extern "C" void kernel_launch(void* const* d_in, const int* in_sizes, int n_in,
                              void* d_out, int out_size) {
    const float* x  = (const float*)d_in[0];
    const float* g  = (const float*)d_in[1];
    const float* w0 = (const float*)d_in[2];
    const float* w1 = (const float*)d_in[3];
    const float* w2 = (const float*)d_in[4];
    const float* w3 = (const float*)d_in[5];
    float* out = (float*)d_out;

    fh *xh, *ah, *bh, *pw0, *pw1, *pw2, *pw3;
    cudaGetSymbolAddress((void**)&xh, g_xh);
    cudaGetSymbolAddress((void**)&ah, g_ah);
    cudaGetSymbolAddress((void**)&bh, g_bh);
    cudaGetSymbolAddress((void**)&pw0, g_w0);
    cudaGetSymbolAddress((void**)&pw1, g_w1);
    cudaGetSymbolAddress((void**)&pw2, g_w2);
    cudaGetSymbolAddress((void**)&pw3, g_w3);

    constexpr int SMEM = 3 * (128 * 128 + 128 * 128);  // 98304 (96KB)
    cudaFuncSetAttribute(hgemm_kernel<2>,
                         cudaFuncAttributeMaxDynamicSharedMemorySize, SMEM);
    cudaFuncSetAttribute(hgemm_kernel<1>,
                         cudaFuncAttributeMaxDynamicSharedMemorySize, SMEM);

    // prep
    rms_kernel<<<NTOK, 256>>>(x, g, xh);
    wsplit_kernel<<<dim3(DHEAD / 32, HID / 32, NHEAD), 256>>>(w0, DHEAD, HID, pw0);
    wsplit2_kernel<<<dim3(HID / 32, HID / 32, 2 * NHEAD), 256>>>(w1, w2, pw1, pw2);
    wsplit_kernel<<<dim3(HID / 32, DHEAD / 32, NHEAD), 256>>>(w3, HID, DHEAD, pw3);

    const size_t actHead = (size_t)NTOK * HID;

    // L0: a = gelu( xn[:,h] @ w0[h] )
    hgemm_kernel<2><<<dim3(NTOK / 128, HID / 128, NHEAD), 128, SMEM>>>(
        xh, (size_t)DHEAD, DTOT, pw0, (size_t)HID * DHEAD, DHEAD,
        ah, nullptr, actHead, HID);
    // L1: b = gelu( a @ w1[h] )
    hgemm_kernel<2><<<dim3(NTOK / 128, HID / 128, NHEAD), 128, SMEM>>>(
        ah, actHead, HID, pw1, (size_t)HID * HID, HID,
        bh, nullptr, actHead, HID);
    // L2: a = gelu( b @ w2[h] )
    hgemm_kernel<2><<<dim3(NTOK / 128, HID / 128, NHEAD), 128, SMEM>>>(
        bh, actHead, HID, pw2, (size_t)HID * HID, HID,
        ah, nullptr, actHead, HID);
    // L3: out[:,h] = a @ w3[h]   fp32 out, no gelu
    hgemm_kernel<1><<<dim3(NTOK / 128, DHEAD / 128, NHEAD), 128, SMEM>>>(
        ah, actHead, HID, pw3, (size_t)DHEAD * HID, HID,
        nullptr, out, (size_t)DHEAD, DTOT);
}